// round 7
// baseline (speedup 1.0000x reference)
#include <cuda_runtime.h>
#include <cuda_bf16.h>

// InnerProduct_541165879452
// lp[r,p] = sum_f w[p,f]^2 * sum_e x[r,f,e]^2
// x: [R=32768, F=64, E=16] f32, w: [10,64] f32, out: [R,10] f32.
//
// Split-F version of the streaming kernel: a PAIR of warps covers the same
// 8 rows, each warp streaming half the features (32 t-iterations). Doubles
// total warps to 8192 (~54/SM) to push DRAM toward saturation. Partials are
// combined through smem with one __syncthreads, then stored coalesced.

#define F_DIM 64
#define P_DIM 10
#define ROW_FLOATS 1024
#define W_STRIDE 12                 // 48B per f-row, float4-aligned
#define THREADS 256                 // 8 warps = 4 row-groups x 2 f-halves
#define ROWS_PER_GROUP 8
#define GROUPS_PER_BLOCK 4
#define ROWS_PER_BLOCK (ROWS_PER_GROUP * GROUPS_PER_BLOCK)   // 32
#define T_PER_WARP 32               // feature-iterations per warp (half of 64)

__global__ __launch_bounds__(THREADS)
void ip_kernel(const float* __restrict__ x,
               const float* __restrict__ w,
               float* __restrict__ out,
               int R)
{
    __shared__ float wsq[F_DIM * W_STRIDE];                 // 3 KB
    __shared__ float part[2][ROWS_PER_BLOCK][P_DIM];        // 2.5 KB

    const int tid = threadIdx.x;

    // Build squared-weight table [f][p] (pad slots zeroed).
    for (int i = tid; i < F_DIM * W_STRIDE; i += THREADS) wsq[i] = 0.0f;
    __syncthreads();
    for (int i = tid; i < P_DIM * F_DIM; i += THREADS) {
        int p = i / F_DIM, f = i % F_DIM;
        float v = w[i];
        wsq[f * W_STRIDE + p] = v * v;
    }
    __syncthreads();

    const int lane  = tid & 31;
    const int wid   = tid >> 5;            // 0..7
    const int group = wid >> 1;            // 0..3 : which 8-row group
    const int half  = wid & 1;             // 0..1 : which feature half
    const int q     = lane & 3;            // quarter within a feature block
    const int rloc  = lane >> 2;           // 0..7 : row within group
    const int rowl  = group * ROWS_PER_GROUP + rloc;        // 0..31 in block
    const int row   = blockIdx.x * ROWS_PER_BLOCK + rowl;
    const int rowc  = row < R ? row : (R - 1);

    const int t0 = half * T_PER_WARP;      // first feature for this warp

    // Lane streams float4 index q + 4t, t = t0 .. t0+31.
    const float4* __restrict__ xp =
        reinterpret_cast<const float4*>(x + (size_t)rowc * ROW_FLOATS) + q + 4 * t0;

    float acc[P_DIM];
#pragma unroll
    for (int p = 0; p < P_DIM; p++) acc[p] = 0.0f;

    for (int tb = 0; tb < T_PER_WARP; tb += 4) {
        float4 v[4];
#pragma unroll
        for (int u = 0; u < 4; u++)
            v[u] = __ldcs(xp + 4 * (tb + u));

#pragma unroll
        for (int u = 0; u < 4; u++) {
            const int f = t0 + tb + u;
            const float4* wr = reinterpret_cast<const float4*>(wsq + f * W_STRIDE);
            const float4 w0 = wr[0], w1 = wr[1], w2 = wr[2];

            float s = v[u].x * v[u].x;
            s = fmaf(v[u].y, v[u].y, s);
            s = fmaf(v[u].z, v[u].z, s);
            s = fmaf(v[u].w, v[u].w, s);

            acc[0] = fmaf(w0.x, s, acc[0]);
            acc[1] = fmaf(w0.y, s, acc[1]);
            acc[2] = fmaf(w0.z, s, acc[2]);
            acc[3] = fmaf(w0.w, s, acc[3]);
            acc[4] = fmaf(w1.x, s, acc[4]);
            acc[5] = fmaf(w1.y, s, acc[5]);
            acc[6] = fmaf(w1.z, s, acc[6]);
            acc[7] = fmaf(w1.w, s, acc[7]);
            acc[8] = fmaf(w2.x, s, acc[8]);
            acc[9] = fmaf(w2.y, s, acc[9]);
        }
    }

    // Quad reduce (2 levels); then q==0 lane of each row writes its partial.
#pragma unroll
    for (int p = 0; p < P_DIM; p++)
        acc[p] += __shfl_xor_sync(0xffffffffu, acc[p], 1);
#pragma unroll
    for (int p = 0; p < P_DIM; p++)
        acc[p] += __shfl_xor_sync(0xffffffffu, acc[p], 2);

    if (q == 0) {
#pragma unroll
        for (int p = 0; p < P_DIM; p++)
            part[half][rowl][p] = acc[p];
    }
    __syncthreads();

    // Combine halves and store: 320 floats per block, coalesced-ish.
    const int base_row = blockIdx.x * ROWS_PER_BLOCK;
    for (int i = tid; i < ROWS_PER_BLOCK * P_DIM; i += THREADS) {
        const int rl = i / P_DIM;
        const int p  = i - rl * P_DIM;
        const int r  = base_row + rl;
        if (r < R)
            out[(size_t)r * P_DIM + p] = part[0][rl][p] + part[1][rl][p];
    }
}

extern "C" void kernel_launch(void* const* d_in, const int* in_sizes, int n_in,
                              void* d_out, int out_size)
{
    const float* x = (const float*)d_in[0];
    const float* w = (const float*)d_in[1];
    float* out = (float*)d_out;

    const int R = in_sizes[0] / ROW_FLOATS;                        // 32768
    const int blocks = (R + ROWS_PER_BLOCK - 1) / ROWS_PER_BLOCK;  // 1024

    ip_kernel<<<blocks, THREADS>>>(x, w, out, R);
}